// round 6
// baseline (speedup 1.0000x reference)
#include <cuda_runtime.h>
#include <math.h>

// ---------------- problem constants ----------------
#define BB     2        // batch
#define EE     256      // encoder channels
#define DD     512      // bottleneck channels
#define T_IN   64000    // input samples
#define FK     20       // encoder/decoder kernel
#define STRIDE 10
#define TC     6403     // encoder frames: (64000 + 40 - 20)/10 + 1
#define TS     6404     // padded time stride (multiple of 4 for float4 alignment)
#define NL     6        // layers per block
#define NBLK   2        // blocks
#define KDW    3        // depthwise kernel
#define BNEPS  1e-5f

// ---------------- scratch (device globals; no allocs allowed) ----------------
__device__ float g_enc[BB * EE * TS];
__device__ float g_hA [BB * EE * TS];
__device__ float g_hB [BB * EE * TS];
__device__ float g_t1 [BB * DD * TS];   // D-channel scratch / mask buffer
__device__ float g_t2 [BB * DD * TS];

// Buffer ids: 0=enc 1=hA 2=hB 3=t1 4=t2
__device__ __forceinline__ float* buf_ptr(int id) {
    switch (id) {
        case 0: return g_enc;
        case 1: return g_hA;
        case 2: return g_hB;
        case 3: return g_t1;
        default: return g_t2;
    }
}

__device__ __forceinline__ float tf32_rna(float x) {
    unsigned r; asm("cvt.rna.tf32.f32 %0, %1;" : "=r"(r) : "f"(x));
    return __uint_as_float(r);
}

// ---------------- encoder: Conv1d(1,E,20,stride=10,pad=20) -> g_enc ----------
__global__ void encoder_k(const float* __restrict__ x,
                          const float* __restrict__ ew,
                          const float* __restrict__ eb)
{
    int idx = blockIdx.x * blockDim.x + threadIdx.x;
    if (idx >= BB * EE * TS) return;
    int t = idx % TS;
    int ce = idx / TS;
    int e = ce % EE;
    int b = ce / EE;
    if (t >= TC) return;
    const float* xr = x + b * T_IN;
    const float* w  = ew + e * FK;
    float acc = __ldg(&eb[e]);
    int p0 = t * STRIDE - FK;
    #pragma unroll
    for (int k = 0; k < FK; k++) {
        int p = p0 + k;
        if (p >= 0 && p < T_IN) acc += __ldg(&w[k]) * __ldg(&xr[p]);
    }
    g_enc[idx] = acc;
}

// ---------------- tensor-core 1x1-conv GEMM (tf32 mma.sync, 3-pass split) ---
// Y[b][m][t] = epilogue( sum_k W[m][k] * X[b][k][t] + bias[m] )
// Split: W*X = Whi*Xhi + Wlo*Xhi + Whi*Xlo  (error ~2^-22)
// mode 0: prelu(alpha) then BN      mode 1: bias only
// mode 2: bias + residual           mode 3: bias + residual + sigmoid-mask*enc
#define BMM  128   // channel tile
#define BNN  128   // time tile
#define BKK  16
#define WPAD 20    // Ws row pad (floats) - conflict-free for A frags
#define XPAD 136   // Xs row pad (floats) - conflict-free for B frags

__global__ __launch_bounds__(256, 2)
void gemm_tc(const float* __restrict__ W,   // [M, Kdim]
             int xid, int yid, int rid,
             int M, int Kdim,
             const float* __restrict__ bias,
             int mode,
             const float* __restrict__ alpha_p,
             const float* __restrict__ bn_g,
             const float* __restrict__ bn_b,
             const float* __restrict__ bn_m,
             const float* __restrict__ bn_v)
{
    const float* X = buf_ptr(xid);
    float*       Y = buf_ptr(yid);

    const int b  = blockIdx.z;
    const int n0 = blockIdx.x * BNN;
    const int m0 = blockIdx.y * BMM;
    const float* Xb = X + (size_t)b * Kdim * TS;

    __shared__ __align__(16) float Ws[BMM][WPAD];   // [m][k]
    __shared__ __align__(16) float Xs[BKK][XPAD];   // [k][t]

    const int tid  = threadIdx.x;
    const int lane = tid & 31;
    const int warp = tid >> 5;
    const int g    = lane >> 2;          // group id 0..7
    const int tg   = lane & 3;           // thread-in-group 0..3
    const int wm   = (warp & 3) * 32;    // warp channel offset
    const int wn   = (warp >> 2) * 64;   // warp time offset

    // loader mappings
    const int xk = tid >> 4;             // 0..15 (k row of X tile)
    const int xc = (tid & 15) * 4;       // 0..60 (col, two float4: xc, xc+64)
    const int wr = tid >> 1;             // 0..127 (m row of W tile)
    const int wk = (tid & 1) * 8;        // 0 or 8 (two float4: wk, wk+4)

    float acc[2][8][4];
    #pragma unroll
    for (int mi = 0; mi < 2; mi++)
        #pragma unroll
        for (int ni = 0; ni < 8; ni++)
            #pragma unroll
            for (int c = 0; c < 4; c++) acc[mi][ni][c] = 0.f;

    const int nkt = Kdim / BKK;
    const float* wbase = &W[(size_t)(m0 + wr) * Kdim + wk];

    for (int pass = 0; pass < 3; pass++) {
        const bool aLo = (pass == 1);
        const bool bLo = (pass == 2);

        for (int kt = 0; kt < nkt; kt++) {
            // ---- global loads (overlap previous tile's math) ----
            const float* wp = wbase + kt * BKK;
            float4 w0 = *reinterpret_cast<const float4*>(wp);
            float4 w1 = *reinterpret_cast<const float4*>(wp + 4);

            const float* xr = &Xb[(size_t)(kt * BKK + xk) * TS];
            float4 x0, x1;
            {
                int c0 = n0 + xc;
                if (c0 + 3 < TC) x0 = *reinterpret_cast<const float4*>(&xr[c0]);
                else {
                    x0.x = (c0+0 < TC) ? xr[c0+0] : 0.f;
                    x0.y = (c0+1 < TC) ? xr[c0+1] : 0.f;
                    x0.z = (c0+2 < TC) ? xr[c0+2] : 0.f;
                    x0.w = (c0+3 < TC) ? xr[c0+3] : 0.f;
                }
                int c1 = c0 + 64;
                if (c1 + 3 < TC) x1 = *reinterpret_cast<const float4*>(&xr[c1]);
                else {
                    x1.x = (c1+0 < TC) ? xr[c1+0] : 0.f;
                    x1.y = (c1+1 < TC) ? xr[c1+1] : 0.f;
                    x1.z = (c1+2 < TC) ? xr[c1+2] : 0.f;
                    x1.w = (c1+3 < TC) ? xr[c1+3] : 0.f;
                }
            }

            // ---- convert to tf32 hi or lo ----
            #define CVT_A(v) (aLo ? tf32_rna((v) - tf32_rna(v)) : tf32_rna(v))
            #define CVT_B(v) (bLo ? tf32_rna((v) - tf32_rna(v)) : tf32_rna(v))
            w0.x = CVT_A(w0.x); w0.y = CVT_A(w0.y); w0.z = CVT_A(w0.z); w0.w = CVT_A(w0.w);
            w1.x = CVT_A(w1.x); w1.y = CVT_A(w1.y); w1.z = CVT_A(w1.z); w1.w = CVT_A(w1.w);
            x0.x = CVT_B(x0.x); x0.y = CVT_B(x0.y); x0.z = CVT_B(x0.z); x0.w = CVT_B(x0.w);
            x1.x = CVT_B(x1.x); x1.y = CVT_B(x1.y); x1.z = CVT_B(x1.z); x1.w = CVT_B(x1.w);
            #undef CVT_A
            #undef CVT_B

            __syncthreads();   // previous tile fully consumed
            Ws[wr][wk + 0] = w0.x; Ws[wr][wk + 1] = w0.y;
            Ws[wr][wk + 2] = w0.z; Ws[wr][wk + 3] = w0.w;
            Ws[wr][wk + 4] = w1.x; Ws[wr][wk + 5] = w1.y;
            Ws[wr][wk + 6] = w1.z; Ws[wr][wk + 7] = w1.w;
            *reinterpret_cast<float4*>(&Xs[xk][xc])      = x0;
            *reinterpret_cast<float4*>(&Xs[xk][xc + 64]) = x1;
            __syncthreads();   // tile ready

            // ---- compute: 2 k8 steps ----
            #pragma unroll
            for (int ks = 0; ks < 2; ks++) {
                const int kb = ks * 8;
                unsigned a[2][4], bf[8][2];
                #pragma unroll
                for (int mi = 0; mi < 2; mi++) {
                    const int mr = wm + mi * 16;
                    a[mi][0] = __float_as_uint(Ws[mr + g    ][kb + tg]);
                    a[mi][1] = __float_as_uint(Ws[mr + g + 8][kb + tg]);
                    a[mi][2] = __float_as_uint(Ws[mr + g    ][kb + tg + 4]);
                    a[mi][3] = __float_as_uint(Ws[mr + g + 8][kb + tg + 4]);
                }
                #pragma unroll
                for (int ni = 0; ni < 8; ni++) {
                    const int nc = wn + ni * 8 + g;
                    bf[ni][0] = __float_as_uint(Xs[kb + tg    ][nc]);
                    bf[ni][1] = __float_as_uint(Xs[kb + tg + 4][nc]);
                }
                #pragma unroll
                for (int mi = 0; mi < 2; mi++)
                    #pragma unroll
                    for (int ni = 0; ni < 8; ni++)
                        asm volatile(
                            "mma.sync.aligned.m16n8k8.row.col.f32.tf32.tf32.f32 "
                            "{%0,%1,%2,%3},{%4,%5,%6,%7},{%8,%9},{%0,%1,%2,%3};"
                            : "+f"(acc[mi][ni][0]), "+f"(acc[mi][ni][1]),
                              "+f"(acc[mi][ni][2]), "+f"(acc[mi][ni][3])
                            : "r"(a[mi][0]), "r"(a[mi][1]), "r"(a[mi][2]), "r"(a[mi][3]),
                              "r"(bf[ni][0]), "r"(bf[ni][1]));
            }
        }
    }

    // ---- epilogue ----
    const float al = (mode == 0) ? __ldg(&alpha_p[0]) : 0.f;
    const float* R = (mode >= 2) ? buf_ptr(rid) : nullptr;

    #pragma unroll
    for (int mi = 0; mi < 2; mi++) {
        #pragma unroll
        for (int h = 0; h < 2; h++) {
            const int mrow = m0 + wm + mi * 16 + g + h * 8;
            const float bia = __ldg(&bias[mrow]);
            float sc = 1.f, sh = 0.f;
            if (mode == 0) {
                sc = __ldg(&bn_g[mrow]) * rsqrtf(__ldg(&bn_v[mrow]) + BNEPS);
                sh = __ldg(&bn_b[mrow]) - __ldg(&bn_m[mrow]) * sc;
            }
            float* yrow = &Y[((size_t)b * M + mrow) * TS];
            const float* rrow = (mode >= 2) ? &R[((size_t)b * M + mrow) * TS] : nullptr;
            const float* erow = (mode == 3) ? &g_enc[((size_t)b * EE + mrow) * TS] : nullptr;

            #pragma unroll
            for (int ni = 0; ni < 8; ni++) {
                const int n = n0 + wn + ni * 8 + 2 * tg;
                float v0 = acc[mi][ni][h * 2 + 0];
                float v1 = acc[mi][ni][h * 2 + 1];
                v0 += bia; v1 += bia;
                if (mode == 0) {
                    v0 = (v0 > 0.f) ? v0 : al * v0;  v0 = v0 * sc + sh;
                    v1 = (v1 > 0.f) ? v1 : al * v1;  v1 = v1 * sc + sh;
                } else if (mode == 2) {
                    if (n     < TC) v0 += rrow[n];
                    if (n + 1 < TC) v1 += rrow[n + 1];
                } else if (mode == 3) {
                    if (n < TC) {
                        v0 += rrow[n];
                        v0 = erow[n] * (1.f / (1.f + expf(-v0)));
                    }
                    if (n + 1 < TC) {
                        v1 += rrow[n + 1];
                        v1 = erow[n + 1] * (1.f / (1.f + expf(-v1)));
                    }
                }
                if (n + 1 < TC) {
                    float2 o = {v0, v1};
                    *reinterpret_cast<float2*>(&yrow[n]) = o;
                } else if (n < TC) {
                    yrow[n] = v0;
                }
            }
        }
    }
}

// ---------------- depthwise K=3 dilated conv + PReLU + BN  (g_t1 -> g_t2) ----
__global__ void dw_fused(const float* __restrict__ wd, const float* __restrict__ bd,
                         const float* __restrict__ alpha_p,
                         const float* __restrict__ g, const float* __restrict__ be,
                         const float* __restrict__ mn, const float* __restrict__ vr,
                         int dil)
{
    int idx = blockIdx.x * blockDim.x + threadIdx.x;
    if (idx >= BB * DD * TS) return;
    int t  = idx % TS;
    int cd = idx / TS;
    int d  = cd % DD;
    if (t >= TC) return;
    const float* xr = g_t1 + (size_t)cd * TS;
    float w0 = __ldg(&wd[d * 3 + 0]), w1 = __ldg(&wd[d * 3 + 1]), w2 = __ldg(&wd[d * 3 + 2]);
    float acc = __ldg(&bd[d]) + w1 * xr[t];
    if (t - dil >= 0) acc += w0 * xr[t - dil];
    if (t + dil < TC) acc += w2 * xr[t + dil];
    float al = __ldg(&alpha_p[0]);
    acc = (acc > 0.f) ? acc : al * acc;
    float sc = __ldg(&g[d]) * rsqrtf(__ldg(&vr[d]) + BNEPS);
    g_t2[idx] = (acc - __ldg(&mn[d])) * sc + __ldg(&be[d]);
}

// ---------------- decoder: ConvTranspose1d(E,1,20,stride=10), slice [FK:T+FK] ---
__global__ void decoder_k(const float* __restrict__ dw,
                          const float* __restrict__ db,
                          float* __restrict__ out)
{
    int idx = blockIdx.x * blockDim.x + threadIdx.x;
    if (idx >= BB * T_IN) return;
    int t = idx % T_IN;
    int b = idx / T_IN;
    int m  = t + FK;
    int t1 = m / STRIDE;
    int k1 = m - t1 * STRIDE;
    int t2 = t1 - 1;
    int k2 = k1 + STRIDE;
    const float* mb = g_t1 + (size_t)b * EE * TS;
    float acc = __ldg(&db[0]);
    #pragma unroll 4
    for (int e = 0; e < EE; e++) {
        const float* mr = &mb[(size_t)e * TS];
        const float* wr = &dw[e * FK];
        acc = fmaf(mr[t1], __ldg(&wr[k1]), acc);
        acc = fmaf(mr[t2], __ldg(&wr[k2]), acc);
    }
    out[idx] = acc;
}

// ---------------- launch (kernel launches ONLY) ----------------
extern "C" void kernel_launch(void* const* d_in, const int* in_sizes, int n_in,
                              void* d_out, int out_size)
{
    const float* x     = (const float*)d_in[0];
    const float* enc_w = (const float*)d_in[1];
    const float* enc_b = (const float*)d_in[2];
    const float* w1    = (const float*)d_in[3];
    const float* b1    = (const float*)d_in[4];
    const float* a1    = (const float*)d_in[5];
    const float* g1    = (const float*)d_in[6];
    const float* be1   = (const float*)d_in[7];
    const float* m1    = (const float*)d_in[8];
    const float* v1    = (const float*)d_in[9];
    const float* wd    = (const float*)d_in[10];
    const float* bd    = (const float*)d_in[11];
    const float* a2    = (const float*)d_in[12];
    const float* g2    = (const float*)d_in[13];
    const float* be2   = (const float*)d_in[14];
    const float* m2    = (const float*)d_in[15];
    const float* v2    = (const float*)d_in[16];
    const float* w2    = (const float*)d_in[17];
    const float* b2    = (const float*)d_in[18];
    const float* dec_w = (const float*)d_in[19];
    const float* dec_b = (const float*)d_in[20];
    float* out = (float*)d_out;

    const int nE = BB * EE * TS;
    const int nD = BB * DD * TS;

    encoder_k<<<(nE + 255) / 256, 256>>>(x, enc_w, enc_b);

    const int NT = (TC + BNN - 1) / BNN;   // 51 time tiles

    for (int bI = 0; bI < NBLK; bI++) {
        const int blk_in = (bI == 0) ? 0 : 1;   // block input == residual source
        const int hbuf   = (bI == 0) ? 1 : 2;   // working h buffer
        for (int i = 0; i < NL; i++) {
            int off = bI * NL + i;
            int in = (i == 0) ? blk_in : hbuf;
            // conv1: E->D, prelu+bn   (in -> t1)
            dim3 gg1(NT, DD / BMM, BB);
            gemm_tc<<<gg1, 256>>>(w1 + (size_t)off * DD * EE, in, 3, 0,
                                  DD, EE, b1 + (size_t)off * DD, 0,
                                  a1 + off,
                                  g1 + (size_t)off * DD, be1 + (size_t)off * DD,
                                  m1 + (size_t)off * DD, v1 + (size_t)off * DD);
            // depthwise + prelu + bn  (t1 -> t2)
            dw_fused<<<(nD + 255) / 256, 256>>>(wd + (size_t)off * DD * KDW,
                                                bd + (size_t)off * DD,
                                                a2 + off,
                                                g2 + (size_t)off * DD, be2 + (size_t)off * DD,
                                                m2 + (size_t)off * DD, v2 + (size_t)off * DD,
                                                1 << i);
            // conv2: D->E  (t2 -> hbuf / t1 on final with mask)
            int mode = (i == NL - 1) ? ((bI == NBLK - 1) ? 3 : 2) : 1;
            int yid  = (mode == 3) ? 3 : hbuf;
            dim3 gg2(NT, EE / BMM, BB);
            gemm_tc<<<gg2, 256>>>(w2 + (size_t)off * EE * DD, 4, yid, blk_in,
                                  EE, DD, b2 + (size_t)off * EE, mode,
                                  nullptr, nullptr, nullptr, nullptr, nullptr);
        }
    }

    // decode (mask fused into final conv2 -> g_t1)
    decoder_k<<<(BB * T_IN + 255) / 256, 256>>>(dec_w, dec_b, out);
}

// round 7
// speedup vs baseline: 1.3648x; 1.3648x over previous
#include <cuda_runtime.h>
#include <math.h>

// ---------------- problem constants ----------------
#define BB     2        // batch
#define EE     256      // encoder channels
#define DD     512      // bottleneck channels
#define T_IN   64000    // input samples
#define FK     20       // encoder/decoder kernel
#define STRIDE 10
#define TC     6403     // encoder frames: (64000 + 40 - 20)/10 + 1
#define TS     6404     // padded time stride (multiple of 4 for float4 alignment)
#define NL     6        // layers per block
#define NBLK   2        // blocks
#define KDW    3        // depthwise kernel
#define BNEPS  1e-5f

// ---------------- scratch (device globals; no allocs allowed) ----------------
__device__ float g_enc[BB * EE * TS];
__device__ float g_hA [BB * EE * TS];
__device__ float g_hB [BB * EE * TS];
__device__ float g_t1 [BB * DD * TS];   // D-channel scratch / mask buffer
__device__ float g_t2 [BB * DD * TS];

// Buffer ids: 0=enc 1=hA 2=hB 3=t1 4=t2
__device__ __forceinline__ float* buf_ptr(int id) {
    switch (id) {
        case 0: return g_enc;
        case 1: return g_hA;
        case 2: return g_hB;
        case 3: return g_t1;
        default: return g_t2;
    }
}

__device__ __forceinline__ float tf32_rna(float x) {
    unsigned r; asm("cvt.rna.tf32.f32 %0, %1;" : "=r"(r) : "f"(x));
    return __uint_as_float(r);
}

// ---------------- encoder: Conv1d(1,E,20,stride=10,pad=20) -> g_enc ----------
__global__ void encoder_k(const float* __restrict__ x,
                          const float* __restrict__ ew,
                          const float* __restrict__ eb)
{
    int idx = blockIdx.x * blockDim.x + threadIdx.x;
    if (idx >= BB * EE * TS) return;
    int t = idx % TS;
    int ce = idx / TS;
    int e = ce % EE;
    int b = ce / EE;
    if (t >= TC) return;
    const float* xr = x + b * T_IN;
    const float* w  = ew + e * FK;
    float acc = __ldg(&eb[e]);
    int p0 = t * STRIDE - FK;
    #pragma unroll
    for (int k = 0; k < FK; k++) {
        int p = p0 + k;
        if (p >= 0 && p < T_IN) acc += __ldg(&w[k]) * __ldg(&xr[p]);
    }
    g_enc[idx] = acc;
}

// ---------------- tensor-core 1x1-conv GEMM (tf32 mma.sync, split-once) -----
// Y[b][m][t] = epilogue( sum_k W[m][k] * X[b][k][t] + bias[m] )
// Per k-tile: build Whi/Wlo, Xhi/Xlo in smem ONCE, then 3 MMA groups:
//   Whi*Xhi + Wlo*Xhi + Whi*Xlo   (residual error ~2^-22)
// Next tile's globals prefetched into registers during MMA compute.
// mode 0: prelu(alpha) then BN      mode 1: bias only
// mode 2: bias + residual           mode 3: bias + residual + sigmoid-mask*enc
#define BMM  128   // channel tile
#define BNN  128   // time tile
#define BKK  16
#define WPAD 20    // Ws row pad (floats) - conflict-free for A frags
#define XPAD 136   // Xs row pad (floats) - conflict-free for B frags

__global__ __launch_bounds__(256, 2)
void gemm_tc(const float* __restrict__ W,   // [M, Kdim]
             int xid, int yid, int rid,
             int M, int Kdim,
             const float* __restrict__ bias,
             int mode,
             const float* __restrict__ alpha_p,
             const float* __restrict__ bn_g,
             const float* __restrict__ bn_b,
             const float* __restrict__ bn_m,
             const float* __restrict__ bn_v)
{
    const float* X = buf_ptr(xid);
    float*       Y = buf_ptr(yid);

    const int b  = blockIdx.z;
    const int n0 = blockIdx.x * BNN;
    const int m0 = blockIdx.y * BMM;
    const float* Xb = X + (size_t)b * Kdim * TS;

    __shared__ __align__(16) float WsH[BMM][WPAD];   // [m][k] hi
    __shared__ __align__(16) float WsL[BMM][WPAD];   // [m][k] lo
    __shared__ __align__(16) float XsH[BKK][XPAD];   // [k][t] hi
    __shared__ __align__(16) float XsL[BKK][XPAD];   // [k][t] lo

    const int tid  = threadIdx.x;
    const int lane = tid & 31;
    const int warp = tid >> 5;
    const int g    = lane >> 2;          // group id 0..7
    const int tg   = lane & 3;           // thread-in-group 0..3
    const int wm   = (warp & 3) * 32;    // warp channel offset
    const int wn   = (warp >> 2) * 64;   // warp time offset

    // loader mappings
    const int xk = tid >> 4;             // 0..15 (k row of X tile)
    const int xc = (tid & 15) * 4;       // 0..60 (col, two float4: xc, xc+64)
    const int wr = tid >> 1;             // 0..127 (m row of W tile)
    const int wk = (tid & 1) * 8;        // 0 or 8 (8 consecutive k)

    float acc[2][8][4];
    #pragma unroll
    for (int mi = 0; mi < 2; mi++)
        #pragma unroll
        for (int ni = 0; ni < 8; ni++)
            #pragma unroll
            for (int c = 0; c < 4; c++) acc[mi][ni][c] = 0.f;

    const int nkt = Kdim / BKK;
    const float* wbase = &W[(size_t)(m0 + wr) * Kdim + wk];

    // staging registers
    float4 w0s, w1s, x0s, x1s;

    // ---- prologue: load tile 0 into staging ----
    {
        w0s = *reinterpret_cast<const float4*>(wbase);
        w1s = *reinterpret_cast<const float4*>(wbase + 4);
        const float* xr = &Xb[(size_t)xk * TS];
        int c0 = n0 + xc;
        if (c0 + 3 < TC) x0s = *reinterpret_cast<const float4*>(&xr[c0]);
        else {
            x0s.x = (c0+0 < TC) ? xr[c0+0] : 0.f;
            x0s.y = (c0+1 < TC) ? xr[c0+1] : 0.f;
            x0s.z = (c0+2 < TC) ? xr[c0+2] : 0.f;
            x0s.w = (c0+3 < TC) ? xr[c0+3] : 0.f;
        }
        int c1 = c0 + 64;
        if (c1 + 3 < TC) x1s = *reinterpret_cast<const float4*>(&xr[c1]);
        else {
            x1s.x = (c1+0 < TC) ? xr[c1+0] : 0.f;
            x1s.y = (c1+1 < TC) ? xr[c1+1] : 0.f;
            x1s.z = (c1+2 < TC) ? xr[c1+2] : 0.f;
            x1s.w = (c1+3 < TC) ? xr[c1+3] : 0.f;
        }
    }

    for (int kt = 0; kt < nkt; kt++) {
        if (kt > 0) __syncthreads();   // previous tile fully consumed

        // ---- convert staged regs to hi/lo and store to smem ----
        {
            float wv[8] = {w0s.x, w0s.y, w0s.z, w0s.w, w1s.x, w1s.y, w1s.z, w1s.w};
            #pragma unroll
            for (int j = 0; j < 8; j++) {
                float hi = tf32_rna(wv[j]);
                WsH[wr][wk + j] = hi;
                WsL[wr][wk + j] = tf32_rna(wv[j] - hi);
            }
            float xv[8] = {x0s.x, x0s.y, x0s.z, x0s.w, x1s.x, x1s.y, x1s.z, x1s.w};
            #pragma unroll
            for (int j = 0; j < 8; j++) {
                float hi = tf32_rna(xv[j]);
                int col = (j < 4) ? (xc + j) : (xc + 60 + j);
                XsH[xk][col] = hi;
                XsL[xk][col] = tf32_rna(xv[j] - hi);
            }
        }
        __syncthreads();               // tile ready

        // ---- prefetch next tile globals (latency hidden under MMAs) ----
        if (kt + 1 < nkt) {
            const float* wp = wbase + (kt + 1) * BKK;
            w0s = *reinterpret_cast<const float4*>(wp);
            w1s = *reinterpret_cast<const float4*>(wp + 4);
            const float* xr = &Xb[(size_t)((kt + 1) * BKK + xk) * TS];
            int c0 = n0 + xc;
            if (c0 + 3 < TC) x0s = *reinterpret_cast<const float4*>(&xr[c0]);
            else {
                x0s.x = (c0+0 < TC) ? xr[c0+0] : 0.f;
                x0s.y = (c0+1 < TC) ? xr[c0+1] : 0.f;
                x0s.z = (c0+2 < TC) ? xr[c0+2] : 0.f;
                x0s.w = (c0+3 < TC) ? xr[c0+3] : 0.f;
            }
            int c1 = c0 + 64;
            if (c1 + 3 < TC) x1s = *reinterpret_cast<const float4*>(&xr[c1]);
            else {
                x1s.x = (c1+0 < TC) ? xr[c1+0] : 0.f;
                x1s.y = (c1+1 < TC) ? xr[c1+1] : 0.f;
                x1s.z = (c1+2 < TC) ? xr[c1+2] : 0.f;
                x1s.w = (c1+3 < TC) ? xr[c1+3] : 0.f;
            }
        }

        // ---- compute: 3 groups x 2 k8-steps x 16 mmas ----
        #pragma unroll
        for (int gp = 0; gp < 3; gp++) {
            const float (*Wsel)[WPAD] = (gp == 1) ? WsL : WsH;
            const float (*Xsel)[XPAD] = (gp == 2) ? XsL : XsH;
            #pragma unroll
            for (int ks = 0; ks < 2; ks++) {
                const int kb = ks * 8;
                unsigned a[2][4], bf[8][2];
                #pragma unroll
                for (int mi = 0; mi < 2; mi++) {
                    const int mr = wm + mi * 16;
                    a[mi][0] = __float_as_uint(Wsel[mr + g    ][kb + tg]);
                    a[mi][1] = __float_as_uint(Wsel[mr + g + 8][kb + tg]);
                    a[mi][2] = __float_as_uint(Wsel[mr + g    ][kb + tg + 4]);
                    a[mi][3] = __float_as_uint(Wsel[mr + g + 8][kb + tg + 4]);
                }
                #pragma unroll
                for (int ni = 0; ni < 8; ni++) {
                    const int nc = wn + ni * 8 + g;
                    bf[ni][0] = __float_as_uint(Xsel[kb + tg    ][nc]);
                    bf[ni][1] = __float_as_uint(Xsel[kb + tg + 4][nc]);
                }
                #pragma unroll
                for (int mi = 0; mi < 2; mi++)
                    #pragma unroll
                    for (int ni = 0; ni < 8; ni++)
                        asm volatile(
                            "mma.sync.aligned.m16n8k8.row.col.f32.tf32.tf32.f32 "
                            "{%0,%1,%2,%3},{%4,%5,%6,%7},{%8,%9},{%0,%1,%2,%3};"
                            : "+f"(acc[mi][ni][0]), "+f"(acc[mi][ni][1]),
                              "+f"(acc[mi][ni][2]), "+f"(acc[mi][ni][3])
                            : "r"(a[mi][0]), "r"(a[mi][1]), "r"(a[mi][2]), "r"(a[mi][3]),
                              "r"(bf[ni][0]), "r"(bf[ni][1]));
            }
        }
    }

    // ---- epilogue ----
    const float al = (mode == 0) ? __ldg(&alpha_p[0]) : 0.f;
    const float* R = (mode >= 2) ? buf_ptr(rid) : nullptr;

    #pragma unroll
    for (int mi = 0; mi < 2; mi++) {
        #pragma unroll
        for (int h = 0; h < 2; h++) {
            const int mrow = m0 + wm + mi * 16 + g + h * 8;
            const float bia = __ldg(&bias[mrow]);
            float sc = 1.f, sh = 0.f;
            if (mode == 0) {
                sc = __ldg(&bn_g[mrow]) * rsqrtf(__ldg(&bn_v[mrow]) + BNEPS);
                sh = __ldg(&bn_b[mrow]) - __ldg(&bn_m[mrow]) * sc;
            }
            float* yrow = &Y[((size_t)b * M + mrow) * TS];
            const float* rrow = (mode >= 2) ? &R[((size_t)b * M + mrow) * TS] : nullptr;
            const float* erow = (mode == 3) ? &g_enc[((size_t)b * EE + mrow) * TS] : nullptr;

            #pragma unroll
            for (int ni = 0; ni < 8; ni++) {
                const int n = n0 + wn + ni * 8 + 2 * tg;
                float v0 = acc[mi][ni][h * 2 + 0];
                float v1 = acc[mi][ni][h * 2 + 1];
                v0 += bia; v1 += bia;
                if (mode == 0) {
                    v0 = (v0 > 0.f) ? v0 : al * v0;  v0 = v0 * sc + sh;
                    v1 = (v1 > 0.f) ? v1 : al * v1;  v1 = v1 * sc + sh;
                } else if (mode == 2) {
                    if (n     < TC) v0 += rrow[n];
                    if (n + 1 < TC) v1 += rrow[n + 1];
                } else if (mode == 3) {
                    if (n < TC) {
                        v0 += rrow[n];
                        v0 = erow[n] * (1.f / (1.f + expf(-v0)));
                    }
                    if (n + 1 < TC) {
                        v1 += rrow[n + 1];
                        v1 = erow[n + 1] * (1.f / (1.f + expf(-v1)));
                    }
                }
                if (n + 1 < TC) {
                    float2 o = {v0, v1};
                    *reinterpret_cast<float2*>(&yrow[n]) = o;
                } else if (n < TC) {
                    yrow[n] = v0;
                }
            }
        }
    }
}

// ---------------- depthwise K=3 dilated conv + PReLU + BN  (g_t1 -> g_t2) ----
__global__ void dw_fused(const float* __restrict__ wd, const float* __restrict__ bd,
                         const float* __restrict__ alpha_p,
                         const float* __restrict__ g, const float* __restrict__ be,
                         const float* __restrict__ mn, const float* __restrict__ vr,
                         int dil)
{
    int idx = blockIdx.x * blockDim.x + threadIdx.x;
    if (idx >= BB * DD * TS) return;
    int t  = idx % TS;
    int cd = idx / TS;
    int d  = cd % DD;
    if (t >= TC) return;
    const float* xr = g_t1 + (size_t)cd * TS;
    float w0 = __ldg(&wd[d * 3 + 0]), w1 = __ldg(&wd[d * 3 + 1]), w2 = __ldg(&wd[d * 3 + 2]);
    float acc = __ldg(&bd[d]) + w1 * xr[t];
    if (t - dil >= 0) acc += w0 * xr[t - dil];
    if (t + dil < TC) acc += w2 * xr[t + dil];
    float al = __ldg(&alpha_p[0]);
    acc = (acc > 0.f) ? acc : al * acc;
    float sc = __ldg(&g[d]) * rsqrtf(__ldg(&vr[d]) + BNEPS);
    g_t2[idx] = (acc - __ldg(&mn[d])) * sc + __ldg(&be[d]);
}

// ---------------- decoder: ConvTranspose1d(E,1,20,stride=10), slice [FK:T+FK] ---
__global__ void decoder_k(const float* __restrict__ dw,
                          const float* __restrict__ db,
                          float* __restrict__ out)
{
    int idx = blockIdx.x * blockDim.x + threadIdx.x;
    if (idx >= BB * T_IN) return;
    int t = idx % T_IN;
    int b = idx / T_IN;
    int m  = t + FK;
    int t1 = m / STRIDE;
    int k1 = m - t1 * STRIDE;
    int t2 = t1 - 1;
    int k2 = k1 + STRIDE;
    const float* mb = g_t1 + (size_t)b * EE * TS;
    float acc = __ldg(&db[0]);
    #pragma unroll 4
    for (int e = 0; e < EE; e++) {
        const float* mr = &mb[(size_t)e * TS];
        const float* wr = &dw[e * FK];
        acc = fmaf(mr[t1], __ldg(&wr[k1]), acc);
        acc = fmaf(mr[t2], __ldg(&wr[k2]), acc);
    }
    out[idx] = acc;
}

// ---------------- launch (kernel launches ONLY) ----------------
extern "C" void kernel_launch(void* const* d_in, const int* in_sizes, int n_in,
                              void* d_out, int out_size)
{
    const float* x     = (const float*)d_in[0];
    const float* enc_w = (const float*)d_in[1];
    const float* enc_b = (const float*)d_in[2];
    const float* w1    = (const float*)d_in[3];
    const float* b1    = (const float*)d_in[4];
    const float* a1    = (const float*)d_in[5];
    const float* g1    = (const float*)d_in[6];
    const float* be1   = (const float*)d_in[7];
    const float* m1    = (const float*)d_in[8];
    const float* v1    = (const float*)d_in[9];
    const float* wd    = (const float*)d_in[10];
    const float* bd    = (const float*)d_in[11];
    const float* a2    = (const float*)d_in[12];
    const float* g2    = (const float*)d_in[13];
    const float* be2   = (const float*)d_in[14];
    const float* m2    = (const float*)d_in[15];
    const float* v2    = (const float*)d_in[16];
    const float* w2    = (const float*)d_in[17];
    const float* b2    = (const float*)d_in[18];
    const float* dec_w = (const float*)d_in[19];
    const float* dec_b = (const float*)d_in[20];
    float* out = (float*)d_out;

    const int nE = BB * EE * TS;
    const int nD = BB * DD * TS;

    encoder_k<<<(nE + 255) / 256, 256>>>(x, enc_w, enc_b);

    const int NT = (TC + BNN - 1) / BNN;   // 51 time tiles

    for (int bI = 0; bI < NBLK; bI++) {
        const int blk_in = (bI == 0) ? 0 : 1;   // block input == residual source
        const int hbuf   = (bI == 0) ? 1 : 2;   // working h buffer
        for (int i = 0; i < NL; i++) {
            int off = bI * NL + i;
            int in = (i == 0) ? blk_in : hbuf;
            // conv1: E->D, prelu+bn   (in -> t1)
            dim3 gg1(NT, DD / BMM, BB);
            gemm_tc<<<gg1, 256>>>(w1 + (size_t)off * DD * EE, in, 3, 0,
                                  DD, EE, b1 + (size_t)off * DD, 0,
                                  a1 + off,
                                  g1 + (size_t)off * DD, be1 + (size_t)off * DD,
                                  m1 + (size_t)off * DD, v1 + (size_t)off * DD);
            // depthwise + prelu + bn  (t1 -> t2)
            dw_fused<<<(nD + 255) / 256, 256>>>(wd + (size_t)off * DD * KDW,
                                                bd + (size_t)off * DD,
                                                a2 + off,
                                                g2 + (size_t)off * DD, be2 + (size_t)off * DD,
                                                m2 + (size_t)off * DD, v2 + (size_t)off * DD,
                                                1 << i);
            // conv2: D->E  (t2 -> hbuf / t1 on final with mask)
            int mode = (i == NL - 1) ? ((bI == NBLK - 1) ? 3 : 2) : 1;
            int yid  = (mode == 3) ? 3 : hbuf;
            dim3 gg2(NT, EE / BMM, BB);
            gemm_tc<<<gg2, 256>>>(w2 + (size_t)off * EE * DD, 4, yid, blk_in,
                                  EE, DD, b2 + (size_t)off * EE, mode,
                                  nullptr, nullptr, nullptr, nullptr, nullptr);
        }
    }

    // decode (mask fused into final conv2 -> g_t1)
    decoder_k<<<(BB * T_IN + 255) / 256, 256>>>(dec_w, dec_b, out);
}

// round 8
// speedup vs baseline: 2.1728x; 1.5920x over previous
#include <cuda_runtime.h>
#include <cuda_bf16.h>
#include <math.h>

// ---------------- problem constants ----------------
#define BB     2
#define EE     256
#define DD     512
#define T_IN   64000
#define FK     20
#define STRIDE 10
#define TC     6403
#define TS     6404
#define NL     6
#define NBLK   2
#define KDW    3
#define BNEPS  1e-5f

// ---------------- scratch ----------------
__device__ float g_enc[BB * EE * TS];
__device__ float g_hA [BB * EE * TS];
__device__ float g_hB [BB * EE * TS];
__device__ float g_t1 [BB * DD * TS];
__device__ float g_t2 [BB * DD * TS];

__device__ __forceinline__ float* buf_ptr(int id) {
    switch (id) {
        case 0: return g_enc;
        case 1: return g_hA;
        case 2: return g_hB;
        case 3: return g_t1;
        default: return g_t2;
    }
}

// pack two floats' bf16(hi-part) as {k1<<16 | k0}
__device__ __forceinline__ unsigned pack_hi(float x0, float x1) {
    unsigned short s0 = __bfloat16_as_ushort(__float2bfloat16_rn(x0));
    unsigned short s1 = __bfloat16_as_ushort(__float2bfloat16_rn(x1));
    return ((unsigned)s1 << 16) | (unsigned)s0;
}
// residual after removing bf16 hi part
__device__ __forceinline__ float bf16_res(float x) {
    return x - __bfloat162float(__float2bfloat16_rn(x));
}

// ---------------- encoder ----------------
__global__ void encoder_k(const float* __restrict__ x,
                          const float* __restrict__ ew,
                          const float* __restrict__ eb)
{
    int idx = blockIdx.x * blockDim.x + threadIdx.x;
    if (idx >= BB * EE * TS) return;
    int t = idx % TS;
    int ce = idx / TS;
    int e = ce % EE;
    int b = ce / EE;
    if (t >= TC) return;
    const float* xr = x + b * T_IN;
    const float* w  = ew + e * FK;
    float acc = __ldg(&eb[e]);
    int p0 = t * STRIDE - FK;
    #pragma unroll
    for (int k = 0; k < FK; k++) {
        int p = p0 + k;
        if (p >= 0 && p < T_IN) acc += __ldg(&w[k]) * __ldg(&xr[p]);
    }
    g_enc[idx] = acc;
}

// ---------------- tensor-core GEMM: bf16 m16n8k16, 3-term split -------------
// Y = epilogue( W*X + bias );  W*X = Wh*Xh + Wl*Xh + Wh*Xl
// Smem holds packed bf16 k-pairs in fragment-friendly layout:
//   Wp[row 128][kpair 8 of 12]  (pad 12: conflict-free frag reads)
//   Xp[kpair 8][col 128 of 136] (pad 136: conflict-free frag reads)
#define BMM  128
#define BNN  128
#define BKK  16
#define WPR  12    // W row stride in uint32 (8 used)
#define XPR  136   // X row stride in uint32 (128 used)

__global__ __launch_bounds__(256, 2)
void gemm_tc(const float* __restrict__ W,   // [M, Kdim] fp32
             int xid, int yid, int rid,
             int M, int Kdim,
             const float* __restrict__ bias,
             int mode,
             const float* __restrict__ alpha_p,
             const float* __restrict__ bn_g,
             const float* __restrict__ bn_b,
             const float* __restrict__ bn_m,
             const float* __restrict__ bn_v)
{
    const float* X = buf_ptr(xid);
    float*       Y = buf_ptr(yid);

    const int b  = blockIdx.z;
    const int n0 = blockIdx.x * BNN;
    const int m0 = blockIdx.y * BMM;
    const float* Xb = X + (size_t)b * Kdim * TS;

    __shared__ __align__(16) unsigned WpH[BMM][WPR];
    __shared__ __align__(16) unsigned WpL[BMM][WPR];
    __shared__ __align__(16) unsigned XpH[8][XPR];
    __shared__ __align__(16) unsigned XpL[8][XPR];

    const int tid  = threadIdx.x;
    const int lane = tid & 31;
    const int warp = tid >> 5;
    const int g    = lane >> 2;
    const int tg   = lane & 3;
    const int wm   = (warp & 3) * 32;
    const int wn   = (warp >> 2) * 64;

    // loader mappings
    const int wr  = tid >> 1;            // W row 0..127
    const int wk  = (tid & 1) * 8;       // k offset 0/8
    const int kp  = tid >> 5;            // X k-pair 0..7
    const int xc  = (tid & 31) * 4;      // X col 0..124

    float acc[2][8][4];
    #pragma unroll
    for (int mi = 0; mi < 2; mi++)
        #pragma unroll
        for (int ni = 0; ni < 8; ni++)
            #pragma unroll
            for (int c = 0; c < 4; c++) acc[mi][ni][c] = 0.f;

    const int nkt = Kdim / BKK;
    const float* wbase = &W[(size_t)(m0 + wr) * Kdim + wk];

    // staging
    float4 w0s, w1s, xa, xbv;

    auto load_x = [&](int ktile, float4& r0, float4& r1) {
        const float* p0 = &Xb[(size_t)(ktile * BKK + 2 * kp) * TS];
        const float* p1 = p0 + TS;
        int c = n0 + xc;
        if (c + 3 < TC) {
            r0 = *reinterpret_cast<const float4*>(&p0[c]);
            r1 = *reinterpret_cast<const float4*>(&p1[c]);
        } else {
            r0.x = (c+0 < TC) ? p0[c+0] : 0.f;  r1.x = (c+0 < TC) ? p1[c+0] : 0.f;
            r0.y = (c+1 < TC) ? p0[c+1] : 0.f;  r1.y = (c+1 < TC) ? p1[c+1] : 0.f;
            r0.z = (c+2 < TC) ? p0[c+2] : 0.f;  r1.z = (c+2 < TC) ? p1[c+2] : 0.f;
            r0.w = (c+3 < TC) ? p0[c+3] : 0.f;  r1.w = (c+3 < TC) ? p1[c+3] : 0.f;
        }
    };

    // prologue
    w0s = *reinterpret_cast<const float4*>(wbase);
    w1s = *reinterpret_cast<const float4*>(wbase + 4);
    load_x(0, xa, xbv);

    for (int kt = 0; kt < nkt; kt++) {
        if (kt > 0) __syncthreads();

        // ---- pack staged data into smem (hi + lo) ----
        {
            float wv[8] = {w0s.x, w0s.y, w0s.z, w0s.w, w1s.x, w1s.y, w1s.z, w1s.w};
            unsigned ph[4], pl[4];
            #pragma unroll
            for (int j = 0; j < 4; j++) {
                ph[j] = pack_hi(wv[2*j], wv[2*j+1]);
                pl[j] = pack_hi(bf16_res(wv[2*j]), bf16_res(wv[2*j+1]));
            }
            *reinterpret_cast<uint4*>(&WpH[wr][wk >> 1]) = *reinterpret_cast<uint4*>(ph);
            *reinterpret_cast<uint4*>(&WpL[wr][wk >> 1]) = *reinterpret_cast<uint4*>(pl);

            float x0[4] = {xa.x, xa.y, xa.z, xa.w};
            float x1[4] = {xbv.x, xbv.y, xbv.z, xbv.w};
            unsigned qh[4], ql[4];
            #pragma unroll
            for (int j = 0; j < 4; j++) {
                qh[j] = pack_hi(x0[j], x1[j]);
                ql[j] = pack_hi(bf16_res(x0[j]), bf16_res(x1[j]));
            }
            *reinterpret_cast<uint4*>(&XpH[kp][xc]) = *reinterpret_cast<uint4*>(qh);
            *reinterpret_cast<uint4*>(&XpL[kp][xc]) = *reinterpret_cast<uint4*>(ql);
        }
        __syncthreads();

        // ---- prefetch next tile ----
        if (kt + 1 < nkt) {
            const float* wp = wbase + (kt + 1) * BKK;
            w0s = *reinterpret_cast<const float4*>(wp);
            w1s = *reinterpret_cast<const float4*>(wp + 4);
            load_x(kt + 1, xa, xbv);
        }

        // ---- A fragments (once per ktile) ----
        unsigned ah[2][4], al[2][4];
        #pragma unroll
        for (int mi = 0; mi < 2; mi++) {
            const int mr = wm + mi * 16 + g;
            ah[mi][0] = WpH[mr    ][tg];
            ah[mi][1] = WpH[mr + 8][tg];
            ah[mi][2] = WpH[mr    ][tg + 4];
            ah[mi][3] = WpH[mr + 8][tg + 4];
            al[mi][0] = WpL[mr    ][tg];
            al[mi][1] = WpL[mr + 8][tg];
            al[mi][2] = WpL[mr    ][tg + 4];
            al[mi][3] = WpL[mr + 8][tg + 4];
        }

        // ---- B fragments + MMAs, in 2 halves of 4 n-tiles ----
        #pragma unroll
        for (int hf = 0; hf < 2; hf++) {
            unsigned bh[4][2], bl[4][2];
            #pragma unroll
            for (int q = 0; q < 4; q++) {
                const int nc = wn + (hf * 4 + q) * 8 + g;
                bh[q][0] = XpH[tg    ][nc];
                bh[q][1] = XpH[tg + 4][nc];
                bl[q][0] = XpL[tg    ][nc];
                bl[q][1] = XpL[tg + 4][nc];
            }
            #define MMA(A, B, mi, q)                                            \
                asm volatile(                                                   \
                    "mma.sync.aligned.m16n8k16.row.col.f32.bf16.bf16.f32 "      \
                    "{%0,%1,%2,%3},{%4,%5,%6,%7},{%8,%9},{%0,%1,%2,%3};"        \
                    : "+f"(acc[mi][hf*4+q][0]), "+f"(acc[mi][hf*4+q][1]),       \
                      "+f"(acc[mi][hf*4+q][2]), "+f"(acc[mi][hf*4+q][3])        \
                    : "r"(A[mi][0]), "r"(A[mi][1]), "r"(A[mi][2]), "r"(A[mi][3]),\
                      "r"(B[q][0]), "r"(B[q][1]))
            #pragma unroll
            for (int mi = 0; mi < 2; mi++)
                #pragma unroll
                for (int q = 0; q < 4; q++) MMA(ah, bh, mi, q);
            #pragma unroll
            for (int mi = 0; mi < 2; mi++)
                #pragma unroll
                for (int q = 0; q < 4; q++) MMA(al, bh, mi, q);
            #pragma unroll
            for (int mi = 0; mi < 2; mi++)
                #pragma unroll
                for (int q = 0; q < 4; q++) MMA(ah, bl, mi, q);
            #undef MMA
        }
    }

    // ---- epilogue ----
    const float alp = (mode == 0) ? __ldg(&alpha_p[0]) : 0.f;
    const float* R = (mode >= 2) ? buf_ptr(rid) : nullptr;

    #pragma unroll
    for (int mi = 0; mi < 2; mi++) {
        #pragma unroll
        for (int h = 0; h < 2; h++) {
            const int mrow = m0 + wm + mi * 16 + g + h * 8;
            const float bia = __ldg(&bias[mrow]);
            float sc = 1.f, sh = 0.f;
            if (mode == 0) {
                sc = __ldg(&bn_g[mrow]) * rsqrtf(__ldg(&bn_v[mrow]) + BNEPS);
                sh = __ldg(&bn_b[mrow]) - __ldg(&bn_m[mrow]) * sc;
            }
            float* yrow = &Y[((size_t)b * M + mrow) * TS];
            const float* rrow = (mode >= 2) ? &R[((size_t)b * M + mrow) * TS] : nullptr;
            const float* erow = (mode == 3) ? &g_enc[((size_t)b * EE + mrow) * TS] : nullptr;

            #pragma unroll
            for (int ni = 0; ni < 8; ni++) {
                const int n = n0 + wn + ni * 8 + 2 * tg;
                float v0 = acc[mi][ni][h * 2 + 0];
                float v1 = acc[mi][ni][h * 2 + 1];
                v0 += bia; v1 += bia;
                if (mode == 0) {
                    v0 = (v0 > 0.f) ? v0 : alp * v0;  v0 = v0 * sc + sh;
                    v1 = (v1 > 0.f) ? v1 : alp * v1;  v1 = v1 * sc + sh;
                } else if (mode == 2) {
                    if (n     < TC) v0 += rrow[n];
                    if (n + 1 < TC) v1 += rrow[n + 1];
                } else if (mode == 3) {
                    if (n < TC) {
                        v0 += rrow[n];
                        v0 = erow[n] * (1.f / (1.f + expf(-v0)));
                    }
                    if (n + 1 < TC) {
                        v1 += rrow[n + 1];
                        v1 = erow[n + 1] * (1.f / (1.f + expf(-v1)));
                    }
                }
                if (n + 1 < TC) {
                    float2 o = {v0, v1};
                    *reinterpret_cast<float2*>(&yrow[n]) = o;
                } else if (n < TC) {
                    yrow[n] = v0;
                }
            }
        }
    }
}

// ---------------- depthwise conv + PReLU + BN  (g_t1 -> g_t2) ----
__global__ void dw_fused(const float* __restrict__ wd, const float* __restrict__ bd,
                         const float* __restrict__ alpha_p,
                         const float* __restrict__ g, const float* __restrict__ be,
                         const float* __restrict__ mn, const float* __restrict__ vr,
                         int dil)
{
    int idx = blockIdx.x * blockDim.x + threadIdx.x;
    if (idx >= BB * DD * TS) return;
    int t  = idx % TS;
    int cd = idx / TS;
    int d  = cd % DD;
    if (t >= TC) return;
    const float* xr = g_t1 + (size_t)cd * TS;
    float w0 = __ldg(&wd[d * 3 + 0]), w1 = __ldg(&wd[d * 3 + 1]), w2 = __ldg(&wd[d * 3 + 2]);
    float acc = __ldg(&bd[d]) + w1 * xr[t];
    if (t - dil >= 0) acc += w0 * xr[t - dil];
    if (t + dil < TC) acc += w2 * xr[t + dil];
    float al = __ldg(&alpha_p[0]);
    acc = (acc > 0.f) ? acc : al * acc;
    float sc = __ldg(&g[d]) * rsqrtf(__ldg(&vr[d]) + BNEPS);
    g_t2[idx] = (acc - __ldg(&mn[d])) * sc + __ldg(&be[d]);
}

// ---------------- decoder ----------------
__global__ void decoder_k(const float* __restrict__ dw,
                          const float* __restrict__ db,
                          float* __restrict__ out)
{
    int idx = blockIdx.x * blockDim.x + threadIdx.x;
    if (idx >= BB * T_IN) return;
    int t = idx % T_IN;
    int b = idx / T_IN;
    int m  = t + FK;
    int t1 = m / STRIDE;
    int k1 = m - t1 * STRIDE;
    int t2 = t1 - 1;
    int k2 = k1 + STRIDE;
    const float* mb = g_t1 + (size_t)b * EE * TS;
    float acc = __ldg(&db[0]);
    #pragma unroll 4
    for (int e = 0; e < EE; e++) {
        const float* mr = &mb[(size_t)e * TS];
        const float* wr = &dw[e * FK];
        acc = fmaf(mr[t1], __ldg(&wr[k1]), acc);
        acc = fmaf(mr[t2], __ldg(&wr[k2]), acc);
    }
    out[idx] = acc;
}

// ---------------- launch ----------------
extern "C" void kernel_launch(void* const* d_in, const int* in_sizes, int n_in,
                              void* d_out, int out_size)
{
    const float* x     = (const float*)d_in[0];
    const float* enc_w = (const float*)d_in[1];
    const float* enc_b = (const float*)d_in[2];
    const float* w1    = (const float*)d_in[3];
    const float* b1    = (const float*)d_in[4];
    const float* a1    = (const float*)d_in[5];
    const float* g1    = (const float*)d_in[6];
    const float* be1   = (const float*)d_in[7];
    const float* m1    = (const float*)d_in[8];
    const float* v1    = (const float*)d_in[9];
    const float* wd    = (const float*)d_in[10];
    const float* bd    = (const float*)d_in[11];
    const float* a2    = (const float*)d_in[12];
    const float* g2    = (const float*)d_in[13];
    const float* be2   = (const float*)d_in[14];
    const float* m2    = (const float*)d_in[15];
    const float* v2    = (const float*)d_in[16];
    const float* w2    = (const float*)d_in[17];
    const float* b2    = (const float*)d_in[18];
    const float* dec_w = (const float*)d_in[19];
    const float* dec_b = (const float*)d_in[20];
    float* out = (float*)d_out;

    const int nE = BB * EE * TS;
    const int nD = BB * DD * TS;

    encoder_k<<<(nE + 255) / 256, 256>>>(x, enc_w, enc_b);

    const int NT = (TC + BNN - 1) / BNN;   // 51 time tiles

    for (int bI = 0; bI < NBLK; bI++) {
        const int blk_in = (bI == 0) ? 0 : 1;
        const int hbuf   = (bI == 0) ? 1 : 2;
        for (int i = 0; i < NL; i++) {
            int off = bI * NL + i;
            int in = (i == 0) ? blk_in : hbuf;
            dim3 gg1(NT, DD / BMM, BB);
            gemm_tc<<<gg1, 256>>>(w1 + (size_t)off * DD * EE, in, 3, 0,
                                  DD, EE, b1 + (size_t)off * DD, 0,
                                  a1 + off,
                                  g1 + (size_t)off * DD, be1 + (size_t)off * DD,
                                  m1 + (size_t)off * DD, v1 + (size_t)off * DD);
            dw_fused<<<(nD + 255) / 256, 256>>>(wd + (size_t)off * DD * KDW,
                                                bd + (size_t)off * DD,
                                                a2 + off,
                                                g2 + (size_t)off * DD, be2 + (size_t)off * DD,
                                                m2 + (size_t)off * DD, v2 + (size_t)off * DD,
                                                1 << i);
            int mode = (i == NL - 1) ? ((bI == NBLK - 1) ? 3 : 2) : 1;
            int yid  = (mode == 3) ? 3 : hbuf;
            dim3 gg2(NT, EE / BMM, BB);
            gemm_tc<<<gg2, 256>>>(w2 + (size_t)off * EE * DD, 4, yid, blk_in,
                                  EE, DD, b2 + (size_t)off * EE, mode,
                                  nullptr, nullptr, nullptr, nullptr, nullptr);
        }
    }

    decoder_k<<<(BB * T_IN + 255) / 256, 256>>>(dec_w, dec_b, out);
}

// round 10
// speedup vs baseline: 2.2237x; 1.0234x over previous
#include <cuda_runtime.h>
#include <cuda_bf16.h>
#include <math.h>

// ---------------- problem constants ----------------
#define BB     2
#define EE     256
#define DD     512
#define T_IN   64000
#define FK     20
#define STRIDE 10
#define TC     6403
#define TS     6404
#define NL     6
#define NBLK   2
#define KDW    3
#define BNEPS  1e-5f

// ---------------- scratch ----------------
__device__ float g_enc[BB * EE * TS];
__device__ float g_hA [BB * EE * TS];
__device__ float g_hB [BB * EE * TS];
__device__ float g_t1 [BB * DD * TS];
__device__ float g_t2 [BB * DD * TS];

__device__ __forceinline__ float* buf_ptr(int id) {
    switch (id) {
        case 0: return g_enc;
        case 1: return g_hA;
        case 2: return g_hB;
        case 3: return g_t1;
        default: return g_t2;
    }
}

__device__ __forceinline__ unsigned pack_hi(float x0, float x1) {
    unsigned short s0 = __bfloat16_as_ushort(__float2bfloat16_rn(x0));
    unsigned short s1 = __bfloat16_as_ushort(__float2bfloat16_rn(x1));
    return ((unsigned)s1 << 16) | (unsigned)s0;
}
__device__ __forceinline__ float bf16_res(float x) {
    return x - __bfloat162float(__float2bfloat16_rn(x));
}

// ---------------- encoder ----------------
__global__ void encoder_k(const float* __restrict__ x,
                          const float* __restrict__ ew,
                          const float* __restrict__ eb)
{
    int idx = blockIdx.x * blockDim.x + threadIdx.x;
    if (idx >= BB * EE * TS) return;
    int t = idx % TS;
    int ce = idx / TS;
    int e = ce % EE;
    int b = ce / EE;
    if (t >= TC) return;
    const float* xr = x + b * T_IN;
    const float* w  = ew + e * FK;
    float acc = __ldg(&eb[e]);
    int p0 = t * STRIDE - FK;
    #pragma unroll
    for (int k = 0; k < FK; k++) {
        int p = p0 + k;
        if (p >= 0 && p < T_IN) acc += __ldg(&w[k]) * __ldg(&xr[p]);
    }
    g_enc[idx] = acc;
}

// ---------------- tensor-core GEMM: bf16 m16n8k16, 3-term split -------------
// Y = epilogue( W*X + bias );  W*X = Wh*Xh + Wl*Xh + Wh*Xl
// Double-buffered smem, ONE __syncthreads per k-tile.
// Tile: 128(M) x 96(N) x 16(K); 8 warps; warp tile 32x48.
#define BMM  128
#define BNN  96
#define BKK  16
#define WPR  12    // W row stride in uint32 (8 used)
#define XPR  104   // X row stride in uint32 (96 used)

__global__ __launch_bounds__(256, 2)
void gemm_tc(const float* __restrict__ W,   // [M, Kdim] fp32
             int xid, int yid, int rid,
             int M, int Kdim,
             const float* __restrict__ bias,
             int mode,
             const float* __restrict__ alpha_p,
             const float* __restrict__ bn_g,
             const float* __restrict__ bn_b,
             const float* __restrict__ bn_m,
             const float* __restrict__ bn_v)
{
    const float* X = buf_ptr(xid);
    float*       Y = buf_ptr(yid);

    const int b  = blockIdx.z;
    const int n0 = blockIdx.x * BNN;
    const int m0 = blockIdx.y * BMM;
    const float* Xb = X + (size_t)b * Kdim * TS;

    __shared__ __align__(16) unsigned WpH[2][BMM][WPR];
    __shared__ __align__(16) unsigned WpL[2][BMM][WPR];
    __shared__ __align__(16) unsigned XpH[2][8][XPR];
    __shared__ __align__(16) unsigned XpL[2][8][XPR];

    const int tid  = threadIdx.x;
    const int lane = tid & 31;
    const int warp = tid >> 5;
    const int g    = lane >> 2;
    const int tg   = lane & 3;
    const int wm   = (warp & 3) * 32;    // warp M offset
    const int wn   = (warp >> 2) * 48;   // warp N offset

    // loader mappings
    const int wr  = tid >> 1;            // W row 0..127
    const int wk  = (tid & 1) * 8;       // k offset 0/8
    const int kp  = warp;                // X k-pair row 0..7 (one per warp)
    const int xc  = lane * 4;            // X col 0..124 (active if < 96)
    const bool xact = (xc < BNN);

    float acc[2][6][4];
    #pragma unroll
    for (int mi = 0; mi < 2; mi++)
        #pragma unroll
        for (int ni = 0; ni < 6; ni++)
            #pragma unroll
            for (int c = 0; c < 4; c++) acc[mi][ni][c] = 0.f;

    const int nkt = Kdim / BKK;
    const float* wbase = &W[(size_t)(m0 + wr) * Kdim + wk];

    float4 w0s, w1s, xa, xbv;

    auto load_x = [&](int ktile) {
        const float* p0 = &Xb[(size_t)(ktile * BKK + 2 * kp) * TS];
        const float* p1 = p0 + TS;
        int c = n0 + xc;
        if (xact) {
            if (c + 3 < TC) {
                xa  = *reinterpret_cast<const float4*>(&p0[c]);
                xbv = *reinterpret_cast<const float4*>(&p1[c]);
            } else {
                xa.x = (c+0 < TC) ? p0[c+0] : 0.f;  xbv.x = (c+0 < TC) ? p1[c+0] : 0.f;
                xa.y = (c+1 < TC) ? p0[c+1] : 0.f;  xbv.y = (c+1 < TC) ? p1[c+1] : 0.f;
                xa.z = (c+2 < TC) ? p0[c+2] : 0.f;  xbv.z = (c+2 < TC) ? p1[c+2] : 0.f;
                xa.w = (c+3 < TC) ? p0[c+3] : 0.f;  xbv.w = (c+3 < TC) ? p1[c+3] : 0.f;
            }
        }
    };

    auto load_w = [&](int ktile) {
        const float* wp = wbase + ktile * BKK;
        w0s = *reinterpret_cast<const float4*>(wp);
        w1s = *reinterpret_cast<const float4*>(wp + 4);
    };

    auto pack_tile = [&](int bufi) {
        float wv[8] = {w0s.x, w0s.y, w0s.z, w0s.w, w1s.x, w1s.y, w1s.z, w1s.w};
        unsigned ph[4], pl[4];
        #pragma unroll
        for (int j = 0; j < 4; j++) {
            ph[j] = pack_hi(wv[2*j], wv[2*j+1]);
            pl[j] = pack_hi(bf16_res(wv[2*j]), bf16_res(wv[2*j+1]));
        }
        *reinterpret_cast<uint4*>(&WpH[bufi][wr][wk >> 1]) = *reinterpret_cast<uint4*>(ph);
        *reinterpret_cast<uint4*>(&WpL[bufi][wr][wk >> 1]) = *reinterpret_cast<uint4*>(pl);

        if (xact) {
            float x0[4] = {xa.x, xa.y, xa.z, xa.w};
            float x1[4] = {xbv.x, xbv.y, xbv.z, xbv.w};
            unsigned qh[4], ql[4];
            #pragma unroll
            for (int j = 0; j < 4; j++) {
                qh[j] = pack_hi(x0[j], x1[j]);
                ql[j] = pack_hi(bf16_res(x0[j]), bf16_res(x1[j]));
            }
            *reinterpret_cast<uint4*>(&XpH[bufi][kp][xc]) = *reinterpret_cast<uint4*>(qh);
            *reinterpret_cast<uint4*>(&XpL[bufi][kp][xc]) = *reinterpret_cast<uint4*>(ql);
        }
    };

    // prologue: tile 0 -> buf 0
    load_w(0); load_x(0);
    pack_tile(0);

    for (int kt = 0; kt < nkt; kt++) {
        __syncthreads();   // buf[kt&1] visible; prior readers of buf[(kt+1)&1] done

        const int cur = kt & 1;
        const bool has_next = (kt + 1 < nkt);
        if (has_next) { load_w(kt + 1); load_x(kt + 1); }

        // ---- A fragments (once per ktile) ----
        unsigned ah[2][4], al[2][4];
        #pragma unroll
        for (int mi = 0; mi < 2; mi++) {
            const int mr = wm + mi * 16 + g;
            ah[mi][0] = WpH[cur][mr    ][tg];
            ah[mi][1] = WpH[cur][mr + 8][tg];
            ah[mi][2] = WpH[cur][mr    ][tg + 4];
            ah[mi][3] = WpH[cur][mr + 8][tg + 4];
            al[mi][0] = WpL[cur][mr    ][tg];
            al[mi][1] = WpL[cur][mr + 8][tg];
            al[mi][2] = WpL[cur][mr    ][tg + 4];
            al[mi][3] = WpL[cur][mr + 8][tg + 4];
        }
        // ---- B fragments ----
        unsigned bh[6][2], bl[6][2];
        #pragma unroll
        for (int q = 0; q < 6; q++) {
            const int nc = wn + q * 8 + g;
            bh[q][0] = XpH[cur][tg    ][nc];
            bh[q][1] = XpH[cur][tg + 4][nc];
            bl[q][0] = XpL[cur][tg    ][nc];
            bl[q][1] = XpL[cur][tg + 4][nc];
        }

        #define MMA(A, B, mi, q)                                                \
            asm volatile(                                                       \
                "mma.sync.aligned.m16n8k16.row.col.f32.bf16.bf16.f32 "          \
                "{%0,%1,%2,%3},{%4,%5,%6,%7},{%8,%9},{%0,%1,%2,%3};"            \
                : "+f"(acc[mi][q][0]), "+f"(acc[mi][q][1]),                     \
                  "+f"(acc[mi][q][2]), "+f"(acc[mi][q][3])                      \
                : "r"(A[mi][0]), "r"(A[mi][1]), "r"(A[mi][2]), "r"(A[mi][3]),   \
                  "r"(B[q][0]), "r"(B[q][1]))
        #pragma unroll
        for (int mi = 0; mi < 2; mi++)
            #pragma unroll
            for (int q = 0; q < 6; q++) MMA(ah, bh, mi, q);
        #pragma unroll
        for (int mi = 0; mi < 2; mi++)
            #pragma unroll
            for (int q = 0; q < 6; q++) MMA(al, bh, mi, q);
        #pragma unroll
        for (int mi = 0; mi < 2; mi++)
            #pragma unroll
            for (int q = 0; q < 6; q++) MMA(ah, bl, mi, q);
        #undef MMA

        if (has_next) pack_tile((kt + 1) & 1);
    }

    // ---- epilogue ----
    const float alp = (mode == 0) ? __ldg(&alpha_p[0]) : 0.f;
    const float* R = (mode >= 2) ? buf_ptr(rid) : nullptr;

    #pragma unroll
    for (int mi = 0; mi < 2; mi++) {
        #pragma unroll
        for (int h = 0; h < 2; h++) {
            const int mrow = m0 + wm + mi * 16 + g + h * 8;
            const float bia = __ldg(&bias[mrow]);
            float sc = 1.f, sh = 0.f;
            if (mode == 0) {
                sc = __ldg(&bn_g[mrow]) * rsqrtf(__ldg(&bn_v[mrow]) + BNEPS);
                sh = __ldg(&bn_b[mrow]) - __ldg(&bn_m[mrow]) * sc;
            }
            float* yrow = &Y[((size_t)b * M + mrow) * TS];
            const float* rrow = (mode >= 2) ? &R[((size_t)b * M + mrow) * TS] : nullptr;
            const float* erow = (mode == 3) ? &g_enc[((size_t)b * EE + mrow) * TS] : nullptr;

            #pragma unroll
            for (int ni = 0; ni < 6; ni++) {
                const int n = n0 + wn + ni * 8 + 2 * tg;
                float v0 = acc[mi][ni][h * 2 + 0];
                float v1 = acc[mi][ni][h * 2 + 1];
                v0 += bia; v1 += bia;
                if (mode == 0) {
                    v0 = (v0 > 0.f) ? v0 : alp * v0;  v0 = v0 * sc + sh;
                    v1 = (v1 > 0.f) ? v1 : alp * v1;  v1 = v1 * sc + sh;
                } else if (mode == 2) {
                    if (n     < TC) v0 += rrow[n];
                    if (n + 1 < TC) v1 += rrow[n + 1];
                } else if (mode == 3) {
                    if (n < TC) {
                        v0 += rrow[n];
                        v0 = erow[n] * (1.f / (1.f + expf(-v0)));
                    }
                    if (n + 1 < TC) {
                        v1 += rrow[n + 1];
                        v1 = erow[n + 1] * (1.f / (1.f + expf(-v1)));
                    }
                }
                if (n + 1 < TC) {
                    float2 o = {v0, v1};
                    *reinterpret_cast<float2*>(&yrow[n]) = o;
                } else if (n < TC) {
                    yrow[n] = v0;
                }
            }
        }
    }
}

// ---------------- depthwise conv + PReLU + BN  (g_t1 -> g_t2) ----
__global__ void dw_fused(const float* __restrict__ wd, const float* __restrict__ bd,
                         const float* __restrict__ alpha_p,
                         const float* __restrict__ g, const float* __restrict__ be,
                         const float* __restrict__ mn, const float* __restrict__ vr,
                         int dil)
{
    int idx = blockIdx.x * blockDim.x + threadIdx.x;
    if (idx >= BB * DD * TS) return;
    int t  = idx % TS;
    int cd = idx / TS;
    int d  = cd % DD;
    if (t >= TC) return;
    const float* xr = g_t1 + (size_t)cd * TS;
    float w0 = __ldg(&wd[d * 3 + 0]), w1 = __ldg(&wd[d * 3 + 1]), w2 = __ldg(&wd[d * 3 + 2]);
    float acc = __ldg(&bd[d]) + w1 * xr[t];
    if (t - dil >= 0) acc += w0 * xr[t - dil];
    if (t + dil < TC) acc += w2 * xr[t + dil];
    float al = __ldg(&alpha_p[0]);
    acc = (acc > 0.f) ? acc : al * acc;
    float sc = __ldg(&g[d]) * rsqrtf(__ldg(&vr[d]) + BNEPS);
    g_t2[idx] = (acc - __ldg(&mn[d])) * sc + __ldg(&be[d]);
}

// ---------------- decoder ----------------
__global__ void decoder_k(const float* __restrict__ dw,
                          const float* __restrict__ db,
                          float* __restrict__ out)
{
    int idx = blockIdx.x * blockDim.x + threadIdx.x;
    if (idx >= BB * T_IN) return;
    int t = idx % T_IN;
    int b = idx / T_IN;
    int m  = t + FK;
    int t1 = m / STRIDE;
    int k1 = m - t1 * STRIDE;
    int t2 = t1 - 1;
    int k2 = k1 + STRIDE;
    const float* mb = g_t1 + (size_t)b * EE * TS;
    float acc = __ldg(&db[0]);
    #pragma unroll 4
    for (int e = 0; e < EE; e++) {
        const float* mr = &mb[(size_t)e * TS];
        const float* wr = &dw[e * FK];
        acc = fmaf(mr[t1], __ldg(&wr[k1]), acc);
        acc = fmaf(mr[t2], __ldg(&wr[k2]), acc);
    }
    out[idx] = acc;
}

// ---------------- launch ----------------
extern "C" void kernel_launch(void* const* d_in, const int* in_sizes, int n_in,
                              void* d_out, int out_size)
{
    const float* x     = (const float*)d_in[0];
    const float* enc_w = (const float*)d_in[1];
    const float* enc_b = (const float*)d_in[2];
    const float* w1    = (const float*)d_in[3];
    const float* b1    = (const float*)d_in[4];
    const float* a1    = (const float*)d_in[5];
    const float* g1    = (const float*)d_in[6];
    const float* be1   = (const float*)d_in[7];
    const float* m1    = (const float*)d_in[8];
    const float* v1    = (const float*)d_in[9];
    const float* wd    = (const float*)d_in[10];
    const float* bd    = (const float*)d_in[11];
    const float* a2    = (const float*)d_in[12];
    const float* g2    = (const float*)d_in[13];
    const float* be2   = (const float*)d_in[14];
    const float* m2    = (const float*)d_in[15];
    const float* v2    = (const float*)d_in[16];
    const float* w2    = (const float*)d_in[17];
    const float* b2    = (const float*)d_in[18];
    const float* dec_w = (const float*)d_in[19];
    const float* dec_b = (const float*)d_in[20];
    float* out = (float*)d_out;

    const int nE = BB * EE * TS;
    const int nD = BB * DD * TS;

    encoder_k<<<(nE + 255) / 256, 256>>>(x, enc_w, enc_b);

    const int NT = (TC + BNN - 1) / BNN;   // 67 time tiles

    for (int bI = 0; bI < NBLK; bI++) {
        const int blk_in = (bI == 0) ? 0 : 1;
        const int hbuf   = (bI == 0) ? 1 : 2;
        for (int i = 0; i < NL; i++) {
            int off = bI * NL + i;
            int in = (i == 0) ? blk_in : hbuf;
            dim3 gg1(NT, DD / BMM, BB);
            gemm_tc<<<gg1, 256>>>(w1 + (size_t)off * DD * EE, in, 3, 0,
                                  DD, EE, b1 + (size_t)off * DD, 0,
                                  a1 + off,
                                  g1 + (size_t)off * DD, be1 + (size_t)off * DD,
                                  m1 + (size_t)off * DD, v1 + (size_t)off * DD);
            dw_fused<<<(nD + 255) / 256, 256>>>(wd + (size_t)off * DD * KDW,
                                                bd + (size_t)off * DD,
                                                a2 + off,
                                                g2 + (size_t)off * DD, be2 + (size_t)off * DD,
                                                m2 + (size_t)off * DD, v2 + (size_t)off * DD,
                                                1 << i);
            int mode = (i == NL - 1) ? ((bI == NBLK - 1) ? 3 : 2) : 1;
            int yid  = (mode == 3) ? 3 : hbuf;
            dim3 gg2(NT, EE / BMM, BB);
            gemm_tc<<<gg2, 256>>>(w2 + (size_t)off * EE * DD, 4, yid, blk_in,
                                  EE, DD, b2 + (size_t)off * EE, mode,
                                  nullptr, nullptr, nullptr, nullptr, nullptr);
        }
    }

    decoder_k<<<(BB * T_IN + 255) / 256, 256>>>(dec_w, dec_b, out);
}